// round 17
// baseline (speedup 1.0000x reference)
#include <cuda_runtime.h>
#include <math.h>
#include <stdint.h>
#include <float.h>

#define BSZ 8
#define TT  8192
#define FF  1024
#define HH  256
#define OO  2
#define MTOK (BSZ * TT)   // 65536 tokens

// ---- scratch (static device globals; no runtime allocation) ----
__device__ float  g_part[1024 * HH];          // 1 MB: per-CTA unnormalized pools
__device__ float2 g_ms[1024];                 // per-CTA (local max, local sumexp)
__device__ uint4  g_w1s[64 * 512];            // 512 KB: W1 bf16 [kt 64][kp 8][n 256]
__device__ uint4  g_wvs[16 * 512];            // 128 KB: Wv bf16 [blk=nb*4+kh][kp 32][n 64]
__device__ uint4  g_wus[16 * 512];            // 128 KB: Wu

// ---- helpers ----
__device__ __forceinline__ uint32_t pbf(float lo, float hi) {
    uint32_t r; asm("cvt.rn.bf16x2.f32 %0, %1, %2;" : "=r"(r) : "f"(hi), "f"(lo)); return r;
}
__device__ __forceinline__ float tanhfast(float x) {
    float y; asm("tanh.approx.f32 %0, %1;" : "=f"(y) : "f"(x)); return y;
}
__device__ __forceinline__ void mma16(float4& d, const uint32_t* a, uint32_t b0, uint32_t b1) {
    asm volatile("mma.sync.aligned.m16n8k16.row.col.f32.bf16.bf16.f32 "
        "{%0,%1,%2,%3}, {%4,%5,%6,%7}, {%8,%9}, {%0,%1,%2,%3};"
        : "+f"(d.x), "+f"(d.y), "+f"(d.z), "+f"(d.w)
        : "r"(a[0]), "r"(a[1]), "r"(a[2]), "r"(a[3]), "r"(b0), "r"(b1));
}
__device__ __forceinline__ uint32_t s2u(const void* p) {
    uint32_t a; asm("{ .reg .u64 t; cvta.to.shared.u64 t, %1; cvt.u32.u64 %0, t; }" : "=r"(a) : "l"(p));
    return a;
}
__device__ __forceinline__ void cpa16(uint32_t dst, const void* src) {
    asm volatile("cp.async.cg.shared.global [%0], [%1], 16;" :: "r"(dst), "l"(src));
}
__device__ __forceinline__ void cp_commit() { asm volatile("cp.async.commit_group;"); }
__device__ __forceinline__ void cp_wait0()  { asm volatile("cp.async.wait_group 0;"); }
__device__ __forceinline__ void cp_wait1()  { asm volatile("cp.async.wait_group 1;"); }

// ============================================================================
// kpre: merged weight pre-conversion (proven).
// ============================================================================
__global__ __launch_bounds__(256)
void kpre(const float* __restrict__ W1, const float* __restrict__ Wv,
          const float* __restrict__ Wu)
{
    const int tid = threadIdx.x;
    if (blockIdx.x < 64) {
        const int kt = blockIdx.x;
        const int kp = tid >> 5, n8 = (tid & 31) << 3;
        const float* r0 = W1 + (size_t)(kt * 16 + 2 * kp) * HH + n8;
        const float4 a0 = *(const float4*)(r0),        a1 = *(const float4*)(r0 + 4);
        const float4 b0 = *(const float4*)(r0 + HH),   b1 = *(const float4*)(r0 + HH + 4);
        g_w1s[kt * 512 + kp * 64 + (n8 >> 2)] =
            make_uint4(pbf(a0.x, b0.x), pbf(a0.y, b0.y), pbf(a0.z, b0.z), pbf(a0.w, b0.w));
        g_w1s[kt * 512 + kp * 64 + (n8 >> 2) + 1] =
            make_uint4(pbf(a1.x, b1.x), pbf(a1.y, b1.y), pbf(a1.z, b1.z), pbf(a1.w, b1.w));
    } else {
        const int blk = blockIdx.x - 64;
        const int nb = blk >> 2, kh = blk & 3;
        const int kp = tid >> 3, n8 = (tid & 7) << 3;
        const size_t off = (size_t)(kh * 64 + 2 * kp) * HH + nb * 64 + n8;
        {
            const float4 a0 = *(const float4*)(Wv + off),      a1 = *(const float4*)(Wv + off + 4);
            const float4 b0 = *(const float4*)(Wv + off + HH), b1 = *(const float4*)(Wv + off + HH + 4);
            g_wvs[blk * 512 + kp * 16 + (n8 >> 2)] =
                make_uint4(pbf(a0.x, b0.x), pbf(a0.y, b0.y), pbf(a0.z, b0.z), pbf(a0.w, b0.w));
            g_wvs[blk * 512 + kp * 16 + (n8 >> 2) + 1] =
                make_uint4(pbf(a1.x, b1.x), pbf(a1.y, b1.y), pbf(a1.z, b1.z), pbf(a1.w, b1.w));
        }
        {
            const float4 a0 = *(const float4*)(Wu + off),      a1 = *(const float4*)(Wu + off + 4);
            const float4 b0 = *(const float4*)(Wu + off + HH), b1 = *(const float4*)(Wu + off + HH + 4);
            g_wus[blk * 512 + kp * 16 + (n8 >> 2)] =
                make_uint4(pbf(a0.x, b0.x), pbf(a0.y, b0.y), pbf(a0.z, b0.z), pbf(a0.w, b0.w));
            g_wus[blk * 512 + kp * 16 + (n8 >> 2) + 1] =
                make_uint4(pbf(a1.x, b1.x), pbf(a1.y, b1.y), pbf(a1.z, b1.z), pbf(a1.w, b1.w));
        }
    }
}

// ============================================================================
// K12: FUSED h-GEMM + gates + ONLINE-SOFTMAX POOLING.
// CTA = 64 tokens, 256 thr, 2 CTAs/SM (grid 1024).
// Phase 1 (proven): h = relu(bags@W1+b1) -> As2 smem [kp 128][72].
// Phase 2 (proven): dual gates GEMM -> per-token logits (in smem).
// Phase 3 (NEW): local softmax (mx, wsum) + unnormalized weighted pool of
//   As2 -> g_part / g_ms. No h or logits ever leave the CTA.
// ============================================================================
#define K1_ASLOT (64 * 36)      // 2304 raw A words / slot
#define K1_BSLOT (16 * 264)     // 4224 B words / slot
#define K1_FBUF  (16 * 72)      // 1152 bf16 A words / buffer
#define P2_BSLOT (32 * 136)     // 4352 words per phase-2 B stage
#define F_WORDS  (9216 + 4 * P2_BSLOT)          // 26624 words
#define F_SMEM   (F_WORDS * 4)                  // 106496 B
__global__ __launch_bounds__(256, 2)
void k12_fused(const float* __restrict__ A, const float* __restrict__ bias,
               const float* __restrict__ bv, const float* __restrict__ bu,
               const float* __restrict__ ww, const float* __restrict__ bw,
               const unsigned char* __restrict__ mask)
{
    extern __shared__ uint32_t sm1[];
    // phase-1 layout (21888 words)
    uint32_t* Araw = sm1;                       // [3][64][36]
    uint32_t* Bst  = sm1 + 3 * K1_ASLOT;        // [3][16][264]
    uint32_t* bfA  = Bst + 3 * K1_BSLOT;        // [2][16][72]
    // phase-2/3 layout (reused post-sync)
    uint32_t* As2  = sm1;                       // [128 kp][72]
    uint32_t* BV2  = sm1 + 9216;                // [2][32][136]
    uint32_t* BU2  = BV2 + 2 * P2_BSLOT;
    __shared__ float red[4][64];
    __shared__ float lsm[64], wsm[64];
    __shared__ float prt[256];
    __shared__ float bcast[2];
    const uint32_t sAraw = s2u(Araw), sBst = s2u(Bst);
    const uint32_t sBV2 = s2u(BV2), sBU2 = s2u(BU2);

    const int tid = threadIdx.x;
    const int lane = tid & 31, wid = tid >> 5;
    const int wm = wid & 1, wn = wid >> 1;       // 2 m-warps x 4 n-warps
    const int g = lane >> 2, tg = lane & 3;
    const size_t mBase = (size_t)blockIdx.x * 64;

    // ---------------- phase 1 (proven) ----------------
    const int ar = tid >> 2, aq = tid & 3;
    const float* aSrc = A + (mBase + ar) * FF + aq * 8;

    auto issue = [&](int kt2) {
        const int slot = kt2 - (kt2 / 3) * 3;
        const uint32_t aw = sAraw + (slot * K1_ASLOT + ar * 36 + aq * 8) * 4;
        cpa16(aw,      aSrc + kt2 * 32);
        cpa16(aw + 16, aSrc + kt2 * 32 + 4);
        #pragma unroll
        for (int j = 0; j < 2; j++) {
            const int c = tid * 2 + j;
            const int row = c >> 6, col = (c & 63) << 2;
            cpa16(sBst + (slot * K1_BSLOT + row * 264 + col) * 4,
                  (const char*)g_w1s + (size_t)(2 * kt2) * 8192 + (size_t)c * 16);
            cpa16(sBst + (slot * K1_BSLOT + (8 + row) * 264 + col) * 4,
                  (const char*)g_w1s + (size_t)(2 * kt2 + 1) * 8192 + (size_t)c * 16);
        }
        cp_commit();
    };
    issue(0); issue(1);

    float4 acc[2][8];
    #pragma unroll
    for (int i = 0; i < 2; i++)
        #pragma unroll
        for (int j = 0; j < 8; j++) acc[i][j] = make_float4(0.f, 0.f, 0.f, 0.f);

    for (int kt2 = 0; kt2 < 32; kt2++) {
        if (kt2 < 31) cp_wait1();
        else cp_wait0();

        const int slot = kt2 - (kt2 / 3) * 3;
        {
            const uint32_t* rw = Araw + slot * K1_ASLOT + ar * 36 + aq * 8;
            const float4 v0 = *(const float4*)rw;
            const float4 v1 = *(const float4*)(rw + 4);
            uint32_t* bf = bfA + (kt2 & 1) * K1_FBUF;
            bf[(aq * 4 + 0) * 72 + ar] = pbf(v0.x, v0.y);
            bf[(aq * 4 + 1) * 72 + ar] = pbf(v0.z, v0.w);
            bf[(aq * 4 + 2) * 72 + ar] = pbf(v1.x, v1.y);
            bf[(aq * 4 + 3) * 72 + ar] = pbf(v1.z, v1.w);
        }
        __syncthreads();
        if (kt2 + 2 < 32) issue(kt2 + 2);

        const uint32_t* ap = bfA + (kt2 & 1) * K1_FBUF;
        const uint32_t* bp = Bst + slot * K1_BSLOT;
        #pragma unroll
        for (int s = 0; s < 2; s++) {
            const int r0 = s * 8 + tg, r1 = s * 8 + tg + 4;
            uint32_t afr[2][4];
            #pragma unroll
            for (int fm = 0; fm < 2; fm++) {
                const int m = wm * 32 + fm * 16 + g;
                afr[fm][0] = ap[r0 * 72 + m];  afr[fm][1] = ap[r0 * 72 + m + 8];
                afr[fm][2] = ap[r1 * 72 + m];  afr[fm][3] = ap[r1 * 72 + m + 8];
            }
            #pragma unroll
            for (int fn = 0; fn < 8; fn++) {
                const int n = wn * 64 + fn * 8 + g;
                const uint32_t b0 = bp[r0 * 264 + n], b1 = bp[r1 * 264 + n];
                mma16(acc[0][fn], afr[0], b0, b1);
                mma16(acc[1][fn], afr[1], b0, b1);
            }
        }
    }
    __syncthreads();   // phase-1 smem reads done before reuse

    // ---- phase-2 stage-0 B prefetch (hidden under epilogue ALU) ----
    auto fill2 = [&](int s2, int pb) {
        const int pass = s2 >> 2, kh = s2 & 3;
        #pragma unroll
        for (int j = 0; j < 2; j++) {
            const int cc = tid * 2 + j;
            const int kp = cc >> 4, nw = (cc & 15) * 4;
            #pragma unroll
            for (int q = 0; q < 2; q++) {
                const int blk = (2 * pass + q) * 4 + kh;
                const uint32_t d = (pb * P2_BSLOT + kp * 136 + q * 64 + nw) * 4;
                cpa16(sBV2 + d, (const char*)g_wvs + (size_t)blk * 8192 + (size_t)cc * 16);
                cpa16(sBU2 + d, (const char*)g_wus + (size_t)blk * 8192 + (size_t)cc * 16);
            }
        }
        cp_commit();
    };
    fill2(0, 0);

    // ---- phase-1 epilogue: bias+relu -> As2 only ----
    #pragma unroll
    for (int fm = 0; fm < 2; fm++) {
        #pragma unroll
        for (int half = 0; half < 2; half++) {
            const int mloc = wm * 32 + fm * 16 + g + half * 8;
            #pragma unroll
            for (int fn = 0; fn < 8; fn++) {
                const int c = wn * 64 + fn * 8 + tg * 2;
                const float v0 = half ? acc[fm][fn].z : acc[fm][fn].x;
                const float v1 = half ? acc[fm][fn].w : acc[fm][fn].y;
                const float h0 = fmaxf(v0 + bias[c], 0.f);
                const float h1 = fmaxf(v1 + bias[c + 1], 0.f);
                As2[(c >> 1) * 72 + mloc] = pbf(h0, h1);
            }
        }
    }
    __syncthreads();   // As2 complete

    // ---------------- phase 2: gated-attention logits ----------------
    float rowsum[4] = {0.f, 0.f, 0.f, 0.f};
    float4 accV[2][4], accU[2][4];

    for (int s2 = 0; s2 < 8; s2++) {
        const int pb = s2 & 1, pass = s2 >> 2, kh = s2 & 3;
        if (s2 < 7) { fill2(s2 + 1, pb ^ 1); cp_wait1(); }
        else cp_wait0();
        __syncthreads();

        if (kh == 0) {
            #pragma unroll
            for (int i = 0; i < 2; i++)
                #pragma unroll
                for (int j = 0; j < 4; j++) {
                    accV[i][j] = make_float4(0.f, 0.f, 0.f, 0.f);
                    accU[i][j] = make_float4(0.f, 0.f, 0.f, 0.f);
                }
        }

        const uint32_t* vp = BV2 + pb * P2_BSLOT;
        const uint32_t* up = BU2 + pb * P2_BSLOT;
        #pragma unroll
        for (int ks = 0; ks < 4; ks++) {
            const int r = ks * 8 + tg;
            const int ra = kh * 32 + r;
            uint32_t afr[2][4];
            #pragma unroll
            for (int fm = 0; fm < 2; fm++) {
                const int m = wm * 32 + fm * 16 + g;
                afr[fm][0] = As2[ra * 72 + m];       afr[fm][1] = As2[ra * 72 + m + 8];
                afr[fm][2] = As2[(ra + 4) * 72 + m]; afr[fm][3] = As2[(ra + 4) * 72 + m + 8];
            }
            #pragma unroll
            for (int fn = 0; fn < 4; fn++) {
                const int n = wn * 32 + fn * 8 + g;
                const uint32_t v0 = vp[r * 136 + n], v1 = vp[(r + 4) * 136 + n];
                const uint32_t u0 = up[r * 136 + n], u1 = up[(r + 4) * 136 + n];
                mma16(accV[0][fn], afr[0], v0, v1);
                mma16(accV[1][fn], afr[1], v0, v1);
                mma16(accU[0][fn], afr[0], u0, u1);
                mma16(accU[1][fn], afr[1], u0, u1);
            }
        }

        if (kh == 3) {
            #pragma unroll
            for (int fm = 0; fm < 2; fm++) {
                #pragma unroll
                for (int fn = 0; fn < 4; fn++) {
                    const int c = pass * 128 + wn * 32 + fn * 8 + tg * 2;
                    const float bv0 = bv[c], bv1 = bv[c + 1];
                    const float bu0 = bu[c], bu1 = bu[c + 1];
                    const float w0 = ww[c],  w1 = ww[c + 1];
                    const float4 av = accV[fm][fn], au = accU[fm][fn];
                    float v, u;
                    v = tanhfast(av.x + bv0); u = 0.5f * tanhfast(0.5f * (au.x + bu0)) + 0.5f;
                    rowsum[fm * 2 + 0] = fmaf(v * u, w0, rowsum[fm * 2 + 0]);
                    v = tanhfast(av.y + bv1); u = 0.5f * tanhfast(0.5f * (au.y + bu1)) + 0.5f;
                    rowsum[fm * 2 + 0] = fmaf(v * u, w1, rowsum[fm * 2 + 0]);
                    v = tanhfast(av.z + bv0); u = 0.5f * tanhfast(0.5f * (au.z + bu0)) + 0.5f;
                    rowsum[fm * 2 + 1] = fmaf(v * u, w0, rowsum[fm * 2 + 1]);
                    v = tanhfast(av.w + bv1); u = 0.5f * tanhfast(0.5f * (au.w + bu1)) + 0.5f;
                    rowsum[fm * 2 + 1] = fmaf(v * u, w1, rowsum[fm * 2 + 1]);
                }
            }
        }
        __syncthreads();
    }

    #pragma unroll
    for (int o = 1; o <= 2; o <<= 1)
        #pragma unroll
        for (int i = 0; i < 4; i++)
            rowsum[i] += __shfl_xor_sync(0xffffffffu, rowsum[i], o);

    if (tg == 0) {
        #pragma unroll
        for (int i = 0; i < 4; i++)
            red[wn][wm * 32 + (i >> 1) * 16 + (i & 1) * 8 + g] = rowsum[i];
    }
    __syncthreads();

    // ---------------- phase 3: local softmax + pooling ----------------
    if (tid < 64) {
        const size_t m = mBase + tid;
        float val = red[0][tid] + red[1][tid] + red[2][tid] + red[3][tid] + bw[0];
        if (mask[m]) val = -1e30f;
        lsm[tid] = val;
    }
    __syncthreads();

    if (tid < 32) {                       // warp 0: local max
        float mx = fmaxf(lsm[tid], lsm[tid + 32]);
        #pragma unroll
        for (int o = 16; o > 0; o >>= 1)
            mx = fmaxf(mx, __shfl_xor_sync(0xffffffffu, mx, o));
        if (tid == 0) bcast[0] = mx;
    }
    __syncthreads();
    const float mx = bcast[0];
    if (tid < 64) wsm[tid] = __expf(lsm[tid] - mx);
    __syncthreads();
    if (tid < 32) {                       // warp 0: local sumexp
        float sum = wsm[tid] + wsm[tid + 32];
        #pragma unroll
        for (int o = 16; o > 0; o >>= 1)
            sum += __shfl_xor_sync(0xffffffffu, sum, o);
        if (tid == 0) bcast[1] = sum;
    }

    // unnormalized pool of As2: thread = (col-pair kp, token-half th)
    {
        const int kp = tid & 127, th = tid >> 7;
        float alo = 0.f, ahi = 0.f;
        #pragma unroll 4
        for (int j = 0; j < 32; j++) {
            const int t = ((j + lane) & 31) + th * 32;   // bank (9*lane+j)%32: distinct
            const uint32_t u = As2[kp * 72 + t];
            const float wt = wsm[t];
            alo = fmaf(wt, __uint_as_float(u << 16), alo);
            ahi = fmaf(wt, __uint_as_float(u & 0xFFFF0000u), ahi);
        }
        if (th == 1) { prt[kp * 2] = alo; prt[kp * 2 + 1] = ahi; }
        __syncthreads();
        if (th == 0) {
            float* dst = &g_part[(size_t)blockIdx.x * 256 + kp * 2];
            dst[0] = alo + prt[kp * 2];
            dst[1] = ahi + prt[kp * 2 + 1];
        }
    }
    if (tid == 0) g_ms[blockIdx.x] = make_float2(mx, bcast[1]);
}

// ============================================================================
// kfinal: per batch, merge 128 CTA partials (online-softmax rescale), then
// logits = slide @ Wc + bc. grid = 8, 256 thr.
// ============================================================================
__global__ __launch_bounds__(256)
void kfinal(const float* __restrict__ Wc, const float* __restrict__ bc,
            float* __restrict__ out)
{
    __shared__ float sred[256];
    __shared__ float scale[128];
    __shared__ float slide[256];
    __shared__ float bb[2];
    const int b = blockIdx.x, tid = threadIdx.x;

    float2 ms = make_float2(-3.4e38f, 0.f);
    if (tid < 128) ms = g_ms[b * 128 + tid];
    sred[tid] = (tid < 128) ? ms.x : -3.4e38f;
    __syncthreads();
    for (int s = 128; s > 0; s >>= 1) {
        if (tid < s) sred[tid] = fmaxf(sred[tid], sred[tid + s]);
        __syncthreads();
    }
    const float M = sred[0];
    __syncthreads();

    float sc = 0.f;
    if (tid < 128) {
        sc = __expf(ms.x - M);
        scale[tid] = sc;
    }
    sred[tid] = (tid < 128) ? sc * ms.y : 0.f;
    __syncthreads();
    for (int s = 128; s > 0; s >>= 1) {
        if (tid < s) sred[tid] += sred[tid + s];
        __syncthreads();
    }
    if (tid == 0) bb[0] = 1.f / sred[0];
    __syncthreads();
    const float inv = bb[0];

    // slide[c] = inv * sum_j scale[j] * part[j][c]
    float s0 = 0.f;
    const float* pp = &g_part[(size_t)b * 128 * 256 + tid];
    #pragma unroll 4
    for (int j = 0; j < 128; j++)
        s0 = fmaf(scale[j], pp[(size_t)j * 256], s0);
    slide[tid] = s0 * inv;
    __syncthreads();

    const int wid = tid >> 5, lane = tid & 31;
    if (wid < 2) {
        float d = 0.f;
        for (int c = lane; c < 256; c += 32) d = fmaf(slide[c], Wc[c * OO + wid], d);
        #pragma unroll
        for (int off = 16; off > 0; off >>= 1) d += __shfl_down_sync(0xffffffffu, d, off);
        if (lane == 0) out[b * OO + wid] = d + bc[wid];
    }
}

// ============================================================================
extern "C" void kernel_launch(void* const* d_in, const int* in_sizes, int n_in,
                              void* d_out, int out_size)
{
    const float*         bags = (const float*)d_in[0];
    const unsigned char* mask = (const unsigned char*)d_in[1];
    const float*         W1   = (const float*)d_in[2];
    const float*         b1   = (const float*)d_in[3];
    const float*         Wv   = (const float*)d_in[4];
    const float*         bv   = (const float*)d_in[5];
    const float*         Wu   = (const float*)d_in[6];
    const float*         bu   = (const float*)d_in[7];
    const float*         ww   = (const float*)d_in[8];
    const float*         bw   = (const float*)d_in[9];
    const float*         Wc   = (const float*)d_in[10];
    const float*         bc   = (const float*)d_in[11];
    float*               out  = (float*)d_out;

    cudaFuncSetAttribute(k12_fused, cudaFuncAttributeMaxDynamicSharedMemorySize, F_SMEM);

    kpre<<<80, 256>>>(W1, Wv, Wu);
    k12_fused<<<MTOK / 64, 256, F_SMEM>>>(bags, b1, bv, bu, ww, bw, mask);
    kfinal<<<BSZ, 256>>>(Wc, bc, out);
}